// round 4
// baseline (speedup 1.0000x reference)
#include <cuda_runtime.h>

#define Bq   16
#define Kq   32
#define Lq   1024
#define Dq   128
#define NEWL 48

#define NEG_INF __int_as_float(0xff800000)

// K1: fused list-build + segmax + pad_mask + event_time. No prep kernel, no scratch.
// grid = (NEWL, B*K), block = 128 (4 warps).
// Each block compacts its own row list from the et row via warp ballots,
// then warp w / lane j reduces float4 column j over rows i = w, w+4, ...
__global__ void __launch_bounds__(Dq) segmax_kernel(const float* __restrict__ h0,
                                                    const float* __restrict__ et,
                                                    const float* __restrict__ npm,
                                                    float* __restrict__ o_h,
                                                    float* __restrict__ o_pm,
                                                    float* __restrict__ o_et) {
    const int s  = blockIdx.x;           // 0..47
    const int bk = blockIdx.y;           // 0..511
    const int b  = bk >> 5;              // K = 32
    const int t  = threadIdx.x;
    const int w  = t >> 5;               // warp 0..3
    const int j  = t & 31;               // lane

    __shared__ int    lst[Lq];
    __shared__ int    scount;
    __shared__ float  sts[4], sms[4];
    __shared__ float4 sacc[Dq];

    if (t == 0) scount = 0;
    __syncthreads();

    // --- build this segment's row list via ballot compaction (et row is L2-hot) ---
    const float* etrow = et + b * Lq;
    float tsum = 0.f;
    #pragma unroll
    for (int k = 0; k < 8; ++k) {
        int l = t + k * Dq;                      // coalesced
        float tv = etrow[l];
        int sg = (tv >= 0.f && tv < 48.f) ? (int)tv : NEWL;
        bool match = (sg == s);
        unsigned mask = __ballot_sync(0xffffffffu, match);
        int base = 0;
        if (j == 0 && mask) base = atomicAdd(&scount, __popc(mask));
        base = __shfl_sync(0xffffffffu, base, 0);
        if (match) {
            lst[base + __popc(mask & ((1u << j) - 1u))] = l;
            tsum += tv;
        }
    }
    __syncthreads();
    const int cnt = scount;

    // --- msum: gathered 0/1 values (exact, order-independent; L2 hits) ---
    const float* mrow = npm + (size_t)bk * Lq;
    float msum = 0.f;
    for (int i = t; i < cnt; i += Dq) msum += mrow[lst[i]];

    // --- segment max: float4 loads, 2 accumulators for per-warp MLP ---
    const float4* base4 = reinterpret_cast<const float4*>(h0 + (size_t)bk * Lq * Dq) + j;
    float4 a0 = make_float4(NEG_INF, NEG_INF, NEG_INF, NEG_INF);
    float4 a1 = a0;
    int i = w;
    for (; i + 4 < cnt; i += 8) {
        float4 v0 = base4[(size_t)lst[i]     * 32];
        float4 v1 = base4[(size_t)lst[i + 4] * 32];
        a0.x = fmaxf(a0.x, v0.x); a0.y = fmaxf(a0.y, v0.y);
        a0.z = fmaxf(a0.z, v0.z); a0.w = fmaxf(a0.w, v0.w);
        a1.x = fmaxf(a1.x, v1.x); a1.y = fmaxf(a1.y, v1.y);
        a1.z = fmaxf(a1.z, v1.z); a1.w = fmaxf(a1.w, v1.w);
    }
    if (i < cnt) {
        float4 v0 = base4[(size_t)lst[i] * 32];
        a0.x = fmaxf(a0.x, v0.x); a0.y = fmaxf(a0.y, v0.y);
        a0.z = fmaxf(a0.z, v0.z); a0.w = fmaxf(a0.w, v0.w);
    }
    a0.x = fmaxf(a0.x, a1.x); a0.y = fmaxf(a0.y, a1.y);
    a0.z = fmaxf(a0.z, a1.z); a0.w = fmaxf(a0.w, a1.w);
    sacc[t] = a0;

    // --- deterministic block reduce of tsum / msum ---
    #pragma unroll
    for (int d = 16; d > 0; d >>= 1) {
        tsum += __shfl_down_sync(0xffffffffu, tsum, d);
        msum += __shfl_down_sync(0xffffffffu, msum, d);
    }
    if (j == 0) { sts[w] = tsum; sms[w] = msum; }
    __syncthreads();

    if (w == 0) {
        float4 v0 = sacc[j], v1 = sacc[32 + j], v2 = sacc[64 + j], v3 = sacc[96 + j];
        float4 r;
        r.x = fmaxf(fmaxf(v0.x, v1.x), fmaxf(v2.x, v3.x));
        r.y = fmaxf(fmaxf(v0.y, v1.y), fmaxf(v2.y, v3.y));
        r.z = fmaxf(fmaxf(v0.z, v1.z), fmaxf(v2.z, v3.z));
        r.w = fmaxf(fmaxf(v0.w, v1.w), fmaxf(v2.w, v3.w));
        if (cnt < Lq) {                   // include_zero (empty segs: -inf -> 0)
            r.x = fmaxf(r.x, 0.f); r.y = fmaxf(r.y, 0.f);
            r.z = fmaxf(r.z, 0.f); r.w = fmaxf(r.w, 0.f);
        }
        reinterpret_cast<float4*>(o_h)[(size_t)bk * NEWL * 32 + s * 32 + j] = r;

        if (j == 0) {
            float denom = fmaxf((float)cnt, 1.f);
            float mt = sts[0] + sts[1] + sts[2] + sts[3];
            float mm = sms[0] + sms[1] + sms[2] + sms[3];
            o_pm[bk * NEWL + s] = mm / denom;
            o_et[bk * NEWL + s] = mt / denom;
        }
    }
}

// K2: almat (B,K,L,48) one-hot write, float4 stores, all 32-bit indexing.
// seg recomputed inline from et (L1/L2 broadcast hits).
__global__ void __launch_bounds__(256) almat_kernel(const float* __restrict__ et,
                                                    float* __restrict__ out_a) {
    unsigned g = blockIdx.x * 256u + threadIdx.x;      // float4 index
    const unsigned total4 = (unsigned)Bq * Kq * Lq * NEWL / 4;   // 6,291,456
    if (g >= total4) return;
    unsigned row = g / 12u;              // (b,k,l) flat — u32 mul-high
    unsigned q   = g - row * 12u;
    unsigned l   = row & (Lq - 1);
    unsigned b   = row >> 15;            // / (K*L), K*L = 2^15
    float tv = __ldg(&et[b * Lq + l]);
    int s = (tv >= 0.f && tv < 48.f) ? (int)tv : NEWL;
    float4 v = make_float4(0.f, 0.f, 0.f, 0.f);
    int o = s - (int)(q * 4u);
    if (o >= 0 && o < 4) (&v.x)[o] = 1.f;
    reinterpret_cast<float4*>(out_a)[g] = v;
}

extern "C" void kernel_launch(void* const* d_in, const int* in_sizes, int n_in,
                              void* d_out, int out_size) {
    const float* h0  = (const float*)d_in[0];
    const float* et  = (const float*)d_in[1];
    const float* npm = (const float*)d_in[2];
    float* out = (float*)d_out;

    float* o_h  = out;                              // (16,32,48,128) = 3,145,728
    float* o_et = out + 3145728;                    // (16,32,48)     =    24,576
    float* o_pm = out + 3145728 + 24576;            // (16,32,48)     =    24,576
    float* o_a  = out + 3145728 + 24576 + 24576;    // (16,32,1024,48)= 25,165,824

    dim3 grid(NEWL, Bq * Kq);
    segmax_kernel<<<grid, Dq>>>(h0, et, npm, o_h, o_pm, o_et);
    almat_kernel<<<(6291456u + 255) / 256, 256>>>(et, o_a);
}

// round 5
// speedup vs baseline: 1.0430x; 1.0430x over previous
#include <cuda_runtime.h>

#define Bq   16
#define Kq   32
#define Lq   1024
#define Dq   128
#define NEWL 48

#define NEG_INF __int_as_float(0xff800000)

#define FMAX4(a, v) { a.x = fmaxf(a.x, v.x); a.y = fmaxf(a.y, v.y); \
                      a.z = fmaxf(a.z, v.z); a.w = fmaxf(a.w, v.w); }

// Fused list-build + segmax + pad_mask + event_time.
// grid = (NEWL/4, B*K), block = 128. Warp w owns segment s = bx*4 + w entirely:
// builds its private row list via ballot compaction, then reduces float4 columns
// (lane = col) over its rows with 4 independent accumulators (MLP=4), and writes
// its 512B output row directly. No cross-warp communication at all.
__global__ void __launch_bounds__(Dq) segmax_kernel(const float* __restrict__ h0,
                                                    const float* __restrict__ et,
                                                    const float* __restrict__ npm,
                                                    float* __restrict__ o_h,
                                                    float* __restrict__ o_pm,
                                                    float* __restrict__ o_et) {
    const int bk = blockIdx.y;            // 0..511
    const int b  = bk >> 5;               // K = 32
    const int w  = threadIdx.x >> 5;      // warp 0..3
    const int j  = threadIdx.x & 31;      // lane
    const int s  = blockIdx.x * 4 + w;    // this warp's segment

    __shared__ int lst[4][Lq];
    int* mylst = lst[w];

    // --- warp-private ballot compaction over the et row (L1/L2-hot, coalesced) ---
    const float* etrow = et + b * Lq;
    float tsum = 0.f;
    int   cnt  = 0;
    #pragma unroll
    for (int k = 0; k < Lq / 32; ++k) {
        int   l  = k * 32 + j;
        float tv = etrow[l];
        int   sg = (tv >= 0.f && tv < 48.f) ? (int)tv : NEWL;
        bool  m  = (sg == s);
        unsigned msk = __ballot_sync(0xffffffffu, m);
        if (m) {
            mylst[cnt + __popc(msk & ((1u << j) - 1u))] = l;
            tsum += tv;
        }
        cnt += __popc(msk);
    }
    __syncwarp();

    // --- segment max: float4 gather, 4 accumulators (MLP=4) ---
    const float4* base4 = reinterpret_cast<const float4*>(h0 + (size_t)bk * Lq * Dq) + j;
    float4 a0 = make_float4(NEG_INF, NEG_INF, NEG_INF, NEG_INF);
    float4 a1 = a0, a2 = a0, a3 = a0;
    int i = 0;
    for (; i + 4 <= cnt; i += 4) {
        int l0 = mylst[i], l1 = mylst[i + 1], l2 = mylst[i + 2], l3 = mylst[i + 3];
        float4 v0 = base4[l0 * 32];
        float4 v1 = base4[l1 * 32];
        float4 v2 = base4[l2 * 32];
        float4 v3 = base4[l3 * 32];
        FMAX4(a0, v0); FMAX4(a1, v1); FMAX4(a2, v2); FMAX4(a3, v3);
    }
    for (; i < cnt; ++i) {
        float4 v = base4[mylst[i] * 32];
        FMAX4(a0, v);
    }
    FMAX4(a0, a1); FMAX4(a2, a3); FMAX4(a0, a2);
    if (cnt < Lq) {                        // include_zero (empty segs: -inf -> 0)
        float4 z = make_float4(0.f, 0.f, 0.f, 0.f);
        FMAX4(a0, z);
    }
    reinterpret_cast<float4*>(o_h)[((size_t)bk * NEWL + s) * 32 + j] = a0;

    // --- msum (exact: 0/1 values) + deterministic-order shuffle reduce ---
    const float* mrow = npm + (size_t)bk * Lq;
    float msum = 0.f;
    for (int i2 = j; i2 < cnt; i2 += 32) msum += mrow[mylst[i2]];
    #pragma unroll
    for (int d = 16; d > 0; d >>= 1) {
        msum += __shfl_down_sync(0xffffffffu, msum, d);
        tsum += __shfl_down_sync(0xffffffffu, tsum, d);
    }
    if (j == 0) {
        float denom = fmaxf((float)cnt, 1.f);
        o_pm[bk * NEWL + s] = msum / denom;
        o_et[bk * NEWL + s] = tsum / denom;
    }
}

// almat (B,K,L,48) one-hot write, float4 stores, 32-bit indexing.
// Measured at ~20us = HBM write-stream floor; left unchanged.
__global__ void __launch_bounds__(256) almat_kernel(const float* __restrict__ et,
                                                    float* __restrict__ out_a) {
    unsigned g = blockIdx.x * 256u + threadIdx.x;                 // float4 index
    const unsigned total4 = (unsigned)Bq * Kq * Lq * NEWL / 4;    // 6,291,456
    if (g >= total4) return;
    unsigned row = g / 12u;               // (b,k,l) flat — u32 mul-high
    unsigned q   = g - row * 12u;
    unsigned l   = row & (Lq - 1);
    unsigned b   = row >> 15;             // / (K*L), K*L = 2^15
    float tv = __ldg(&et[b * Lq + l]);
    int s = (tv >= 0.f && tv < 48.f) ? (int)tv : NEWL;
    float4 v = make_float4(0.f, 0.f, 0.f, 0.f);
    int o = s - (int)(q * 4u);
    if (o >= 0 && o < 4) (&v.x)[o] = 1.f;
    reinterpret_cast<float4*>(out_a)[g] = v;
}

extern "C" void kernel_launch(void* const* d_in, const int* in_sizes, int n_in,
                              void* d_out, int out_size) {
    const float* h0  = (const float*)d_in[0];
    const float* et  = (const float*)d_in[1];
    const float* npm = (const float*)d_in[2];
    float* out = (float*)d_out;

    float* o_h  = out;                              // (16,32,48,128) = 3,145,728
    float* o_et = out + 3145728;                    // (16,32,48)     =    24,576
    float* o_pm = out + 3145728 + 24576;            // (16,32,48)     =    24,576
    float* o_a  = out + 3145728 + 24576 + 24576;    // (16,32,1024,48)= 25,165,824

    dim3 grid(NEWL / 4, Bq * Kq);
    segmax_kernel<<<grid, Dq>>>(h0, et, npm, o_h, o_pm, o_et);
    almat_kernel<<<(6291456u + 255) / 256, 256>>>(et, o_a);
}